// round 11
// baseline (speedup 1.0000x reference)
#include <cuda_runtime.h>
#include <cuda_fp16.h>
#include <cuda_bf16.h>

#define N_NODES 100000
#define N_EDGES 1600000
#define IN_CH   48
#define OUT_CH  64
#define V8_PER_ROW (IN_CH / 8)   // 6 chunks of 8 fp16 channels (16B) per row
#define NB ((N_NODES + 1023) / 1024)   // 98 scan blocks

// -------- scratch (allocation-free: __device__ globals) --------
// INVARIANT: g_deg == 0 and g_cur == 0 at kernel_launch entry. CUDA zero-
// inits device globals; k_scan1 re-zeroes both after/before use, so the
// invariant holds on every call (correctness run, capture, every replay).
__device__ __align__(16) __half g_x16[N_NODES * IN_CH];  // fp16 copy of x
__device__ __align__(16) __half g_h1[N_NODES * IN_CH];   // fp16 intermediate
__device__ __align__(16) float  g_h2[N_NODES * IN_CH];   // fp32 (feeds GEMM)
__device__ float g_dinv[N_NODES];
__device__ int   g_deg[N_NODES];
__device__ int   g_off[N_NODES];     // block-LOCAL exclusive scan of deg
__device__ int   g_cur[N_NODES];     // relative cursor (zeroed)
__device__ uint2 g_edge[N_EDGES];    // CSR-by-dst: {src index, fp32 norm}
__device__ int   g_bsum[128];        // per-block degree sums
__device__ int   g_is64;             // 1 if edge_index is int64, 0 if int32

// packed f32x2 FMA (FFMA2 — only reachable via PTX fma.rn.f32x2)
#define FMA_F32X2(d, a, b, c) \
    asm("fma.rn.f32x2 %0, %1, %2, %3;" : "=l"(d) : "l"(a), "l"(b), "l"(c))

// inclusive scan of the 98 block sums into sh[0..127]; call with >=128 threads
__device__ __forceinline__ void boff_scan(int* sh) {
    int tid = threadIdx.x;
    if (tid < 128) sh[tid] = (tid < NB) ? g_bsum[tid] : 0;
    __syncthreads();
#pragma unroll
    for (int o = 1; o < 128; o <<= 1) {
        int v = (tid >= o && tid < 128) ? sh[tid - o] : 0;
        __syncthreads();
        if (tid < 128) sh[tid] += v;
        __syncthreads();
    }
}
#define BOFF(sh, blk) ((blk) > 0 ? (sh)[(blk) - 1] : 0)

// -------- 1. fused: dtype sniff + degree histogram + x -> fp16 --------
__global__ void k_build(const int* __restrict__ ei32,
                        const float4* __restrict__ x) {
    __shared__ int s_is64;
    if (threadIdx.x == 0) {
        // int64 LE indices < 2^31 have every odd int32 word == 0
        int nz = 0;
#pragma unroll
        for (int k = 0; k < 128; k++) nz |= ei32[2 * k + 1];
        s_is64 = (nz == 0) ? 1 : 0;
        if (blockIdx.x == 0) g_is64 = s_is64;
    }
    __syncthreads();
    const int is64 = s_is64;

    int i = blockIdx.x * blockDim.x + threadIdx.x;
    int stride = gridDim.x * blockDim.x;

    // degree histogram over destination (col) indices (RED, fire-and-forget)
    for (int e = i; e < N_EDGES; e += stride) {
        int c = is64 ? (int)((const long long*)ei32)[N_EDGES + e]
                     : ei32[N_EDGES + e];
        c = min(max(c, 0), N_NODES - 1);
        atomicAdd(&g_deg[c], 1);
    }

    // x -> fp16 streaming conversion
    uint2* x16 = reinterpret_cast<uint2*>(g_x16);
    const int n4 = N_NODES * IN_CH / 4;
    for (int j = i; j < n4; j += stride) {
        float4 v = x[j];
        __half2 p0 = __floats2half2_rn(v.x, v.y);
        __half2 p1 = __floats2half2_rn(v.z, v.w);
        uint2 pk;
        pk.x = *reinterpret_cast<unsigned int*>(&p0);
        pk.y = *reinterpret_cast<unsigned int*>(&p1);
        x16[j] = pk;
    }
}

// -------- 2. per-block exclusive scan + dinv + deg/cur cleanup --------
__global__ void k_scan1() {
    __shared__ int warp_sums[32];
    int i = blockIdx.x * 1024 + threadIdx.x;
    int v = (i < N_NODES) ? g_deg[i] : 0;
    if (i < N_NODES) {
        g_dinv[i] = (v > 0) ? rsqrtf((float)v) : 0.0f;
        g_deg[i] = 0;   // restore invariant for the next replay
        g_cur[i] = 0;   // relative cursor for k_place
    }

    int lane = threadIdx.x & 31;
    int warp = threadIdx.x >> 5;
    int s = v;
#pragma unroll
    for (int o = 1; o < 32; o <<= 1) {
        int t = __shfl_up_sync(0xffffffffu, s, o);
        if (lane >= o) s += t;
    }
    if (lane == 31) warp_sums[warp] = s;
    __syncthreads();
    if (warp == 0) {
        int ws = warp_sums[lane];
#pragma unroll
        for (int o = 1; o < 32; o <<= 1) {
            int t = __shfl_up_sync(0xffffffffu, ws, o);
            if (lane >= o) ws += t;
        }
        warp_sums[lane] = ws;
    }
    __syncthreads();
    int excl = s - v + ((warp > 0) ? warp_sums[warp - 1] : 0);
    if (i < N_NODES) g_off[i] = excl;                        // block-LOCAL excl
    if (threadIdx.x == 1023) g_bsum[blockIdx.x] = excl + v;  // block total
}

// -------- 3. counting-sort: 2 edges/thread, packed {src, w} records --------
__global__ void k_place(const void* __restrict__ eiraw) {
    __shared__ int sh[128];
    boff_scan(sh);

    int base_e = (blockIdx.x * blockDim.x + threadIdx.x) * 2;
    const int is64 = g_is64;

#pragma unroll
    for (int u = 0; u < 2; u++) {
        int e = base_e + u;
        if (e >= N_EDGES) break;
        int r, c;
        if (is64) {
            const long long* ei = (const long long*)eiraw;
            r = (int)ei[e];
            c = (int)ei[N_EDGES + e];
        } else {
            const int* ei = (const int*)eiraw;
            r = ei[e];
            c = ei[N_EDGES + e];
        }
        r = min(max(r, 0), N_NODES - 1);
        c = min(max(c, 0), N_NODES - 1);
        float w = g_dinv[r] * g_dinv[c];
        int base = g_off[c] + BOFF(sh, c >> 10);
        int pos = base + atomicAdd(&g_cur[c], 1);
        uint2 rec;
        rec.x = (unsigned int)r;
        rec.y = __float_as_uint(w);
        g_edge[pos] = rec;
    }
}

// -------- 4. propagation: 6 lanes/node, 16B fp16 gathers, fp32 acc --------
// Edge record carries the weight: chain is edge-load -> row-load only.
// STAGE 0: src = g_x16 -> g_h1 (fp16). STAGE 1: src = g_h1 -> g_h2 (fp32).
template <int STAGE>
__global__ void k_prop() {
    __shared__ int sh[128];
    boff_scan(sh);

    const uint4* __restrict__ src = reinterpret_cast<const uint4*>(
        STAGE == 0 ? g_x16 : g_h1);

    int t = blockIdx.x * blockDim.x + threadIdx.x;
    int node = t / V8_PER_ROW;
    int lane = t - node * V8_PER_ROW;
    if (node >= N_NODES) return;

    int beg = g_off[node] + BOFF(sh, node >> 10);
    int nid1 = node + 1;
    int end = (nid1 == N_NODES)
                  ? sh[127]
                  : g_off[nid1] + BOFF(sh, nid1 >> 10);

    float acc[8];
#pragma unroll
    for (int j = 0; j < 8; j++) acc[j] = 0.f;

#define ACCUM_EDGE(rv, wv)                                                   \
    do {                                                                     \
        float2 f0 = __half22float2(*reinterpret_cast<__half2*>(&(rv).x));    \
        float2 f1 = __half22float2(*reinterpret_cast<__half2*>(&(rv).y));    \
        float2 f2 = __half22float2(*reinterpret_cast<__half2*>(&(rv).z));    \
        float2 f3 = __half22float2(*reinterpret_cast<__half2*>(&(rv).w));    \
        acc[0] += f0.x * (wv); acc[1] += f0.y * (wv);                        \
        acc[2] += f1.x * (wv); acc[3] += f1.y * (wv);                        \
        acc[4] += f2.x * (wv); acc[5] += f2.y * (wv);                        \
        acc[6] += f3.x * (wv); acc[7] += f3.y * (wv);                        \
    } while (0)

    int k = beg;
    for (; k + 4 <= end; k += 4) {
        uint2 e0 = g_edge[k],     e1 = g_edge[k + 1];
        uint2 e2 = g_edge[k + 2], e3 = g_edge[k + 3];
        uint4 r0 = src[e0.x * V8_PER_ROW + lane];
        uint4 r1 = src[e1.x * V8_PER_ROW + lane];
        uint4 r2 = src[e2.x * V8_PER_ROW + lane];
        uint4 r3 = src[e3.x * V8_PER_ROW + lane];
        float w0 = __uint_as_float(e0.y), w1 = __uint_as_float(e1.y);
        float w2 = __uint_as_float(e2.y), w3 = __uint_as_float(e3.y);
        ACCUM_EDGE(r0, w0);
        ACCUM_EDGE(r1, w1);
        ACCUM_EDGE(r2, w2);
        ACCUM_EDGE(r3, w3);
    }
    for (; k < end; k++) {
        uint2 e0 = g_edge[k];
        uint4 r0 = src[e0.x * V8_PER_ROW + lane];
        float w0 = __uint_as_float(e0.y);
        ACCUM_EDGE(r0, w0);
    }
#undef ACCUM_EDGE

    if (STAGE == 0) {
        __half2 p0 = __floats2half2_rn(acc[0], acc[1]);
        __half2 p1 = __floats2half2_rn(acc[2], acc[3]);
        __half2 p2 = __floats2half2_rn(acc[4], acc[5]);
        __half2 p3 = __floats2half2_rn(acc[6], acc[7]);
        uint4 pk;
        pk.x = *reinterpret_cast<unsigned int*>(&p0);
        pk.y = *reinterpret_cast<unsigned int*>(&p1);
        pk.z = *reinterpret_cast<unsigned int*>(&p2);
        pk.w = *reinterpret_cast<unsigned int*>(&p3);
        reinterpret_cast<uint4*>(g_h1)[node * V8_PER_ROW + lane] = pk;
    } else {
        float4* drow = reinterpret_cast<float4*>(g_h2 + node * IN_CH + lane * 8);
        drow[0] = make_float4(acc[0], acc[1], acc[2], acc[3]);
        drow[1] = make_float4(acc[4], acc[5], acc[6], acc[7]);
    }
}

// -------- 5. dense epilogue: out = g_h2 @ W + b (packed f32x2 FMA) --------
__global__ void k_gemm(const float* __restrict__ W,
                       const float* __restrict__ b,
                       float* __restrict__ out) {
    __shared__ __align__(16) float Ws[IN_CH * OUT_CH];
    __shared__ __align__(16) float bs[OUT_CH];
    for (int i = threadIdx.x; i < IN_CH * OUT_CH; i += blockDim.x) Ws[i] = W[i];
    if (threadIdx.x < OUT_CH) bs[threadIdx.x] = b[threadIdx.x];
    __syncthreads();

    int n = blockIdx.x * blockDim.x + threadIdx.x;
    if (n >= N_NODES) return;

    unsigned long long acc[OUT_CH / 2];
    const unsigned long long* bs2 = reinterpret_cast<const unsigned long long*>(bs);
#pragma unroll
    for (int j = 0; j < OUT_CH / 2; j++) acc[j] = bs2[j];

    const float4* hr = reinterpret_cast<const float4*>(g_h2 + (long long)n * IN_CH);
#pragma unroll
    for (int k4 = 0; k4 < IN_CH / 4; k4++) {
        float4 xv = hr[k4];
        unsigned long long ax, ay, az, aw;
        unsigned int bx = __float_as_uint(xv.x), by = __float_as_uint(xv.y);
        unsigned int bz = __float_as_uint(xv.z), bw = __float_as_uint(xv.w);
        asm("mov.b64 %0, {%1, %1};" : "=l"(ax) : "r"(bx));
        asm("mov.b64 %0, {%1, %1};" : "=l"(ay) : "r"(by));
        asm("mov.b64 %0, {%1, %1};" : "=l"(az) : "r"(bz));
        asm("mov.b64 %0, {%1, %1};" : "=l"(aw) : "r"(bw));
        const unsigned long long* w0 =
            reinterpret_cast<const unsigned long long*>(&Ws[(k4 * 4 + 0) * OUT_CH]);
        const unsigned long long* w1 =
            reinterpret_cast<const unsigned long long*>(&Ws[(k4 * 4 + 1) * OUT_CH]);
        const unsigned long long* w2 =
            reinterpret_cast<const unsigned long long*>(&Ws[(k4 * 4 + 2) * OUT_CH]);
        const unsigned long long* w3 =
            reinterpret_cast<const unsigned long long*>(&Ws[(k4 * 4 + 3) * OUT_CH]);
#pragma unroll
        for (int j = 0; j < OUT_CH / 2; j++) {
            FMA_F32X2(acc[j], ax, w0[j], acc[j]);
            FMA_F32X2(acc[j], ay, w1[j], acc[j]);
            FMA_F32X2(acc[j], az, w2[j], acc[j]);
            FMA_F32X2(acc[j], aw, w3[j], acc[j]);
        }
    }

    uint4* o = reinterpret_cast<uint4*>(out + (long long)n * OUT_CH);
#pragma unroll
    for (int j = 0; j < OUT_CH / 4; j++) {
        unsigned int p, q, r, s;
        asm("mov.b64 {%0, %1}, %2;" : "=r"(p), "=r"(q) : "l"(acc[2 * j]));
        asm("mov.b64 {%0, %1}, %2;" : "=r"(r), "=r"(s) : "l"(acc[2 * j + 1]));
        uint4 v; v.x = p; v.y = q; v.z = r; v.w = s;
        o[j] = v;
    }
}

extern "C" void kernel_launch(void* const* d_in, const int* in_sizes, int n_in,
                              void* d_out, int out_size) {
    const float* x  = (const float*)d_in[0];   // [N_NODES, IN_CH]
    const void*  ei = d_in[1];                 // [2, N_EDGES] int32 OR int64
    const float* W  = (const float*)d_in[2];   // [IN_CH, OUT_CH]
    const float* b  = (const float*)d_in[3];   // [OUT_CH]
    float*       out = (float*)d_out;          // [N_NODES, OUT_CH]

    // CSR build (scan3 fused into consumers)
    k_build<<<(N_EDGES + 511) / 512, 512>>>((const int*)ei, (const float4*)x);
    k_scan1<<<NB, 1024>>>();
    k_place<<<(N_EDGES / 2 + 511) / 512, 512>>>(ei);

    // two propagation steps: h1 = A x16 ; h2 = A h1
    const int threads = 384;                 // 64 nodes per block * 6 lanes
    const int total = N_NODES * V8_PER_ROW;
    int grid = (total + threads - 1) / threads;
    k_prop<0><<<grid, threads>>>();
    k_prop<1><<<grid, threads>>>();

    // out = h2 @ W + b
    k_gemm<<<(N_NODES + 127) / 128, 128>>>(W, b, out);
}

// round 12
// speedup vs baseline: 1.1235x; 1.1235x over previous
#include <cuda_runtime.h>
#include <cuda_fp16.h>
#include <cuda_bf16.h>

#define N_NODES 100000
#define N_EDGES 1600000
#define IN_CH   48
#define OUT_CH  64
#define V8_PER_ROW (IN_CH / 8)   // 6 chunks of 8 fp16 channels (16B) per row
#define NB ((N_NODES + 1023) / 1024)   // 98 scan blocks

// -------- scratch (allocation-free: __device__ globals) --------
// INVARIANT: g_deg == 0 at kernel_launch entry. CUDA zero-inits device
// globals; k_scan1 re-zeroes after consuming, so the invariant holds on
// every call (correctness run, capture, every replay).
__device__ __align__(16) __half g_x16[N_NODES * IN_CH];  // fp16 copy of x
__device__ __align__(16) __half g_h1[N_NODES * IN_CH];   // fp16 intermediate
__device__ __align__(16) float  g_h2[N_NODES * IN_CH];   // fp32 (feeds GEMM)
__device__ float g_dinv[N_NODES];
__device__ int   g_deg[N_NODES];
__device__ int   g_off[N_NODES + 1];
__device__ int   g_cur[N_NODES];
__device__ int   g_src[N_EDGES];   // CSR-by-dst: source node per slot
__device__ int   g_bsum[128];      // per-block degree sums
__device__ int   g_is64;           // 1 if edge_index is int64, 0 if int32

// packed f32x2 FMA (FFMA2 — only reachable via PTX fma.rn.f32x2)
#define FMA_F32X2(d, a, b, c) \
    asm("fma.rn.f32x2 %0, %1, %2, %3;" : "=l"(d) : "l"(a), "l"(b), "l"(c))

// -------- 1. fused: dtype sniff + degree histogram + x -> fp16 --------
__global__ void k_build(const int* __restrict__ ei32,
                        const float4* __restrict__ x) {
    __shared__ int s_is64;
    if (threadIdx.x == 0) {
        // int64 LE indices < 2^31 have every odd int32 word == 0
        int nz = 0;
#pragma unroll
        for (int k = 0; k < 128; k++) nz |= ei32[2 * k + 1];
        s_is64 = (nz == 0) ? 1 : 0;
        if (blockIdx.x == 0) g_is64 = s_is64;
    }
    __syncthreads();
    const int is64 = s_is64;

    int i = blockIdx.x * blockDim.x + threadIdx.x;
    int stride = gridDim.x * blockDim.x;

    // degree histogram over destination (col) indices
    for (int e = i; e < N_EDGES; e += stride) {
        int c = is64 ? (int)((const long long*)ei32)[N_EDGES + e]
                     : ei32[N_EDGES + e];
        c = min(max(c, 0), N_NODES - 1);
        atomicAdd(&g_deg[c], 1);
    }

    // x -> fp16 streaming conversion
    uint2* x16 = reinterpret_cast<uint2*>(g_x16);
    const int n4 = N_NODES * IN_CH / 4;
    for (int j = i; j < n4; j += stride) {
        float4 v = x[j];
        __half2 p0 = __floats2half2_rn(v.x, v.y);
        __half2 p1 = __floats2half2_rn(v.z, v.w);
        uint2 pk;
        pk.x = *reinterpret_cast<unsigned int*>(&p0);
        pk.y = *reinterpret_cast<unsigned int*>(&p1);
        x16[j] = pk;
    }
}

// -------- 2a. per-block exclusive scan + dinv + deg cleanup --------
__global__ void k_scan1() {
    __shared__ int warp_sums[32];
    int i = blockIdx.x * 1024 + threadIdx.x;
    int v = (i < N_NODES) ? g_deg[i] : 0;
    if (i < N_NODES) {
        g_dinv[i] = (v > 0) ? rsqrtf((float)v) : 0.0f;
        g_deg[i] = 0;   // restore invariant for the next replay
    }

    int lane = threadIdx.x & 31;
    int warp = threadIdx.x >> 5;
    int s = v;
#pragma unroll
    for (int o = 1; o < 32; o <<= 1) {
        int t = __shfl_up_sync(0xffffffffu, s, o);
        if (lane >= o) s += t;
    }
    if (lane == 31) warp_sums[warp] = s;
    __syncthreads();
    if (warp == 0) {
        int ws = warp_sums[lane];
#pragma unroll
        for (int o = 1; o < 32; o <<= 1) {
            int t = __shfl_up_sync(0xffffffffu, ws, o);
            if (lane >= o) ws += t;
        }
        warp_sums[lane] = ws;
    }
    __syncthreads();
    int excl = s - v + ((warp > 0) ? warp_sums[warp - 1] : 0);
    if (i < N_NODES) g_off[i] = excl;                        // block-local excl
    if (threadIdx.x == 1023) g_bsum[blockIdx.x] = excl + v;  // block total
}

// -------- 2b. block-sum scan (redundant per block) + offset add --------
__global__ void k_scan3() {
    __shared__ int sh[128];
    int tid = threadIdx.x;
    if (tid < 128) sh[tid] = (tid < NB) ? g_bsum[tid] : 0;
    __syncthreads();
    for (int o = 1; o < 128; o <<= 1) {
        int x = (tid >= o && tid < 128) ? sh[tid - o] : 0;
        __syncthreads();
        if (tid < 128) sh[tid] += x;
        __syncthreads();
    }
    int i = blockIdx.x * blockDim.x + tid;
    if (i < N_NODES) {
        int blk = i >> 10;
        int boff = (blk > 0) ? sh[blk - 1] : 0;
        int o = g_off[i] + boff;
        g_off[i] = o;
        g_cur[i] = o;
    }
    if (blockIdx.x == 0 && tid == 0) g_off[N_NODES] = sh[127];
}

// -------- 3. counting-sort by destination: 2 edges/thread (2x atomic MLP) --
__global__ void k_place(const void* __restrict__ eiraw) {
    int base = (blockIdx.x * blockDim.x + threadIdx.x) * 2;
    if (base >= N_EDGES) return;          // N_EDGES even -> base+1 also valid
    const int is64 = g_is64;
    int r0, c0, r1, c1;
    if (is64) {
        const long long* ei = (const long long*)eiraw;
        r0 = (int)ei[base];
        r1 = (int)ei[base + 1];
        c0 = (int)ei[N_EDGES + base];
        c1 = (int)ei[N_EDGES + base + 1];
    } else {
        const int* ei = (const int*)eiraw;
        r0 = ei[base];
        r1 = ei[base + 1];
        c0 = ei[N_EDGES + base];
        c1 = ei[N_EDGES + base + 1];
    }
    r0 = min(max(r0, 0), N_NODES - 1);
    c0 = min(max(c0, 0), N_NODES - 1);
    r1 = min(max(r1, 0), N_NODES - 1);
    c1 = min(max(c1, 0), N_NODES - 1);
    int p0 = atomicAdd(&g_cur[c0], 1);    // both atomics in flight together
    int p1 = atomicAdd(&g_cur[c1], 1);
    g_src[p0] = r0;
    g_src[p1] = r1;
}

// -------- 4. propagation: 6 lanes/node, 16B fp16 gathers, fp32 acc --------
// STAGE 0: src = g_x16 -> g_h1 (fp16). STAGE 1: src = g_h1 -> g_h2 (fp32).
template <int STAGE>
__global__ void k_prop() {
    const uint4* __restrict__ src = reinterpret_cast<const uint4*>(
        STAGE == 0 ? g_x16 : g_h1);

    int t = blockIdx.x * blockDim.x + threadIdx.x;
    int node = t / V8_PER_ROW;
    int lane = t - node * V8_PER_ROW;
    if (node >= N_NODES) return;
    int beg = g_off[node];
    int end = g_off[node + 1];
    float dc = g_dinv[node];

    float acc[8];
#pragma unroll
    for (int j = 0; j < 8; j++) acc[j] = 0.f;

#define ACCUM_EDGE(rv, wv)                                                   \
    do {                                                                     \
        float2 f0 = __half22float2(*reinterpret_cast<__half2*>(&(rv).x));    \
        float2 f1 = __half22float2(*reinterpret_cast<__half2*>(&(rv).y));    \
        float2 f2 = __half22float2(*reinterpret_cast<__half2*>(&(rv).z));    \
        float2 f3 = __half22float2(*reinterpret_cast<__half2*>(&(rv).w));    \
        acc[0] += f0.x * (wv); acc[1] += f0.y * (wv);                        \
        acc[2] += f1.x * (wv); acc[3] += f1.y * (wv);                        \
        acc[4] += f2.x * (wv); acc[5] += f2.y * (wv);                        \
        acc[6] += f3.x * (wv); acc[7] += f3.y * (wv);                        \
    } while (0)

    int k = beg;
    for (; k + 4 <= end; k += 4) {
        int s0 = g_src[k], s1 = g_src[k + 1], s2 = g_src[k + 2], s3 = g_src[k + 3];
        float w0 = g_dinv[s0] * dc, w1 = g_dinv[s1] * dc;
        float w2 = g_dinv[s2] * dc, w3 = g_dinv[s3] * dc;
        uint4 r0 = src[s0 * V8_PER_ROW + lane];
        uint4 r1 = src[s1 * V8_PER_ROW + lane];
        uint4 r2 = src[s2 * V8_PER_ROW + lane];
        uint4 r3 = src[s3 * V8_PER_ROW + lane];
        ACCUM_EDGE(r0, w0);
        ACCUM_EDGE(r1, w1);
        ACCUM_EDGE(r2, w2);
        ACCUM_EDGE(r3, w3);
    }
    for (; k < end; k++) {
        int s0 = g_src[k];
        float w0 = g_dinv[s0] * dc;
        uint4 r0 = src[s0 * V8_PER_ROW + lane];
        ACCUM_EDGE(r0, w0);
    }
#undef ACCUM_EDGE

    if (STAGE == 0) {
        __half2 p0 = __floats2half2_rn(acc[0], acc[1]);
        __half2 p1 = __floats2half2_rn(acc[2], acc[3]);
        __half2 p2 = __floats2half2_rn(acc[4], acc[5]);
        __half2 p3 = __floats2half2_rn(acc[6], acc[7]);
        uint4 pk;
        pk.x = *reinterpret_cast<unsigned int*>(&p0);
        pk.y = *reinterpret_cast<unsigned int*>(&p1);
        pk.z = *reinterpret_cast<unsigned int*>(&p2);
        pk.w = *reinterpret_cast<unsigned int*>(&p3);
        reinterpret_cast<uint4*>(g_h1)[node * V8_PER_ROW + lane] = pk;
    } else {
        float4* drow = reinterpret_cast<float4*>(g_h2 + node * IN_CH + lane * 8);
        drow[0] = make_float4(acc[0], acc[1], acc[2], acc[3]);
        drow[1] = make_float4(acc[4], acc[5], acc[6], acc[7]);
    }
}

// -------- 5. dense epilogue: out = g_h2 @ W + b --------
// 2 nodes per thread, 32 outputs each: every shared W load feeds TWO FFMA2s,
// halving the LDS-issue bound that dominated the 1-node-per-thread version.
__global__ void k_gemm(const float* __restrict__ W,
                       const float* __restrict__ b,
                       float* __restrict__ out) {
    __shared__ __align__(16) float Ws[IN_CH * OUT_CH];
    __shared__ __align__(16) float bs[OUT_CH];
    for (int i = threadIdx.x; i < IN_CH * OUT_CH; i += blockDim.x) Ws[i] = W[i];
    if (threadIdx.x < OUT_CH) bs[threadIdx.x] = b[threadIdx.x];
    __syncthreads();

    int gid = blockIdx.x * blockDim.x + threadIdx.x;
    int p = gid >> 1;           // node pair index
    int half = gid & 1;         // output half: [half*32, half*32+32)
    int nA = p * 2;
    if (nA >= N_NODES) return;  // N_NODES even -> nA+1 also valid
    int nB = nA + 1;

    unsigned long long accA[16], accB[16];
    const unsigned long long* bs2 =
        reinterpret_cast<const unsigned long long*>(bs + half * 32);
#pragma unroll
    for (int j = 0; j < 16; j++) { accA[j] = bs2[j]; accB[j] = bs2[j]; }

    const float4* hA = reinterpret_cast<const float4*>(g_h2 + (long long)nA * IN_CH);
    const float4* hB = reinterpret_cast<const float4*>(g_h2 + (long long)nB * IN_CH);

#pragma unroll
    for (int k4 = 0; k4 < IN_CH / 4; k4++) {
        float4 a4 = hA[k4];
        float4 b4 = hB[k4];
        float av[4] = {a4.x, a4.y, a4.z, a4.w};
        float bv[4] = {b4.x, b4.y, b4.z, b4.w};
#pragma unroll
        for (int kk = 0; kk < 4; kk++) {
            int k = k4 * 4 + kk;
            unsigned long long ax, bx;
            unsigned int au = __float_as_uint(av[kk]);
            unsigned int bu = __float_as_uint(bv[kk]);
            asm("mov.b64 %0, {%1, %1};" : "=l"(ax) : "r"(au));
            asm("mov.b64 %0, {%1, %1};" : "=l"(bx) : "r"(bu));
            const unsigned long long* wrow = reinterpret_cast<const unsigned long long*>(
                Ws + k * OUT_CH + half * 32);
#pragma unroll
            for (int j = 0; j < 16; j++) {
                unsigned long long wv = wrow[j];   // one LDS serves both nodes
                FMA_F32X2(accA[j], ax, wv, accA[j]);
                FMA_F32X2(accB[j], bx, wv, accB[j]);
            }
        }
    }

    float* oA = out + (long long)nA * OUT_CH + half * 32;
    float* oB = out + (long long)nB * OUT_CH + half * 32;
#pragma unroll
    for (int j = 0; j < 8; j++) {
        uint4 vA, vB;
        asm("mov.b64 {%0, %1}, %2;" : "=r"(vA.x), "=r"(vA.y) : "l"(accA[2 * j]));
        asm("mov.b64 {%0, %1}, %2;" : "=r"(vA.z), "=r"(vA.w) : "l"(accA[2 * j + 1]));
        asm("mov.b64 {%0, %1}, %2;" : "=r"(vB.x), "=r"(vB.y) : "l"(accB[2 * j]));
        asm("mov.b64 {%0, %1}, %2;" : "=r"(vB.z), "=r"(vB.w) : "l"(accB[2 * j + 1]));
        reinterpret_cast<uint4*>(oA)[j] = vA;
        reinterpret_cast<uint4*>(oB)[j] = vB;
    }
}

extern "C" void kernel_launch(void* const* d_in, const int* in_sizes, int n_in,
                              void* d_out, int out_size) {
    const float* x  = (const float*)d_in[0];   // [N_NODES, IN_CH]
    const void*  ei = d_in[1];                 // [2, N_EDGES] int32 OR int64
    const float* W  = (const float*)d_in[2];   // [IN_CH, OUT_CH]
    const float* b  = (const float*)d_in[3];   // [OUT_CH]
    float*       out = (float*)d_out;          // [N_NODES, OUT_CH]

    // CSR build
    k_build<<<(N_EDGES + 511) / 512, 512>>>((const int*)ei, (const float4*)x);
    k_scan1<<<NB, 1024>>>();
    k_scan3<<<(N_NODES + 255) / 256, 256>>>();
    k_place<<<(N_EDGES / 2 + 511) / 512, 512>>>(ei);

    // two propagation steps: h1 = A x16 ; h2 = A h1
    const int threads = 192;                 // 32 nodes per block * 6 lanes
    const int total = N_NODES * V8_PER_ROW;
    int grid = (total + threads - 1) / threads;
    k_prop<0><<<grid, threads>>>();
    k_prop<1><<<grid, threads>>>();

    // out = h2 @ W + b  (one thread covers 2 nodes x 32 outputs)
    k_gemm<<<(N_NODES + 127) / 128, 128>>>(W, b, out);
}